// round 1
// baseline (speedup 1.0000x reference)
#include <cuda_runtime.h>
#include <math_constants.h>

// Single-query attention: y = softmax(K @ q) @ V
//   q: [256] f32, K: [131072, 256] f32, V: [131072, 256] f32 -> y: [256] f32
// HBM-bound: 256MB streamed once. Flash-decode split: pass1 per-CTA online
// softmax partials, pass2 combine.

#define M_TOTAL   131072
#define DIM       256
#define NUM_CTAS  1024
#define ROWS_PER_CTA (M_TOTAL / NUM_CTAS)     // 128
#define NWARPS    8
#define ROWS_PER_WARP (ROWS_PER_CTA / NWARPS) // 16

// Scratch (allocation-free): ~1 MB
__device__ float g_part[NUM_CTAS][DIM];
__device__ float g_m[NUM_CTAS];
__device__ float g_l[NUM_CTAS];

__global__ __launch_bounds__(256)
void sqa_pass1(const float* __restrict__ q,
               const float* __restrict__ K,
               const float* __restrict__ V) {
    const int tid  = threadIdx.x;
    const int warp = tid >> 5;
    const int lane = tid & 31;

    // q in registers: lane covers columns [lane*4, lane*4+3] and [128+lane*4, ...]
    const float4 q0 = reinterpret_cast<const float4*>(q)[lane];
    const float4 q1 = reinterpret_cast<const float4*>(q)[lane + 32];

    const int row0 = blockIdx.x * ROWS_PER_CTA + warp * ROWS_PER_WARP;

    float m = -CUDART_INF_F;
    float l = 0.0f;
    float4 a0 = make_float4(0.f, 0.f, 0.f, 0.f);
    float4 a1 = make_float4(0.f, 0.f, 0.f, 0.f);

    #pragma unroll 2
    for (int r = 0; r < ROWS_PER_WARP; ++r) {
        const size_t row = (size_t)(row0 + r);
        const float4* Kr = reinterpret_cast<const float4*>(K + row * DIM);
        const float4* Vr = reinterpret_cast<const float4*>(V + row * DIM);

        // issue all loads up front for MLP
        const float4 k0 = Kr[lane];
        const float4 k1 = Kr[lane + 32];
        const float4 v0 = Vr[lane];
        const float4 v1 = Vr[lane + 32];

        float d = k0.x * q0.x + k0.y * q0.y + k0.z * q0.z + k0.w * q0.w
                + k1.x * q1.x + k1.y * q1.y + k1.z * q1.z + k1.w * q1.w;
        #pragma unroll
        for (int off = 16; off > 0; off >>= 1)
            d += __shfl_xor_sync(0xffffffffu, d, off);

        const float mnew  = fmaxf(m, d);
        const float scale = __expf(m - mnew);   // exp(-inf)=0 on first iter
        const float w     = __expf(d - mnew);
        l = l * scale + w;
        a0.x = a0.x * scale + w * v0.x;
        a0.y = a0.y * scale + w * v0.y;
        a0.z = a0.z * scale + w * v0.z;
        a0.w = a0.w * scale + w * v0.w;
        a1.x = a1.x * scale + w * v1.x;
        a1.y = a1.y * scale + w * v1.y;
        a1.z = a1.z * scale + w * v1.z;
        a1.w = a1.w * scale + w * v1.w;
        m = mnew;
    }

    // Merge 8 warps within the CTA
    __shared__ float s_m[NWARPS];
    __shared__ float s_l[NWARPS];
    __shared__ float s_acc[NWARPS][DIM];

    if (lane == 0) { s_m[warp] = m; s_l[warp] = l; }
    float* dst = s_acc[warp];
    dst[lane * 4 + 0]       = a0.x;
    dst[lane * 4 + 1]       = a0.y;
    dst[lane * 4 + 2]       = a0.z;
    dst[lane * 4 + 3]       = a0.w;
    dst[128 + lane * 4 + 0] = a1.x;
    dst[128 + lane * 4 + 1] = a1.y;
    dst[128 + lane * 4 + 2] = a1.z;
    dst[128 + lane * 4 + 3] = a1.w;
    __syncthreads();

    // CTA max (every thread computes redundantly over 8 values)
    float bm = s_m[0];
    #pragma unroll
    for (int w2 = 1; w2 < NWARPS; ++w2) bm = fmaxf(bm, s_m[w2]);

    // Each thread owns one output column c = tid
    float y = 0.0f;
    float L = 0.0f;
    #pragma unroll
    for (int w2 = 0; w2 < NWARPS; ++w2) {
        const float sf = __expf(s_m[w2] - bm);
        y += s_acc[w2][tid] * sf;
        L += s_l[w2] * sf;
    }

    g_part[blockIdx.x][tid] = y;
    if (tid == 0) { g_m[blockIdx.x] = bm; g_l[blockIdx.x] = L; }
}

__global__ __launch_bounds__(256)
void sqa_pass2(float* __restrict__ out) {
    __shared__ float sf[NUM_CTAS];
    __shared__ float red[256];
    const int t = threadIdx.x;

    // global max over CTA maxes
    float lm = -CUDART_INF_F;
    for (int i = t; i < NUM_CTAS; i += 256) lm = fmaxf(lm, g_m[i]);
    red[t] = lm;
    __syncthreads();
    #pragma unroll
    for (int s = 128; s > 0; s >>= 1) {
        if (t < s) red[t] = fmaxf(red[t], red[t + s]);
        __syncthreads();
    }
    const float gmax = red[0];
    __syncthreads();

    // scale factors + global L
    float ll = 0.0f;
    for (int i = t; i < NUM_CTAS; i += 256) {
        const float e = __expf(g_m[i] - gmax);
        sf[i] = e;
        ll += g_l[i] * e;
    }
    red[t] = ll;
    __syncthreads();
    #pragma unroll
    for (int s = 128; s > 0; s >>= 1) {
        if (t < s) red[t] += red[t + s];
        __syncthreads();
    }
    const float invL = 1.0f / red[0];
    __syncthreads();

    // combine partials: thread t owns output column t (coalesced across i)
    float acc = 0.0f;
    #pragma unroll 8
    for (int i = 0; i < NUM_CTAS; ++i)
        acc += g_part[i][t] * sf[i];
    out[t] = acc * invL;
}

extern "C" void kernel_launch(void* const* d_in, const int* in_sizes, int n_in,
                              void* d_out, int out_size) {
    const float* q = (const float*)d_in[0];
    const float* K = (const float*)d_in[1];
    const float* V = (const float*)d_in[2];
    float* out = (float*)d_out;

    sqa_pass1<<<NUM_CTAS, 256>>>(q, K, V);
    sqa_pass2<<<1, 256>>>(out);
}

// round 2
// speedup vs baseline: 2.0192x; 2.0192x over previous
#include <cuda_runtime.h>
#include <math_constants.h>

// Single-query attention: y = softmax(K @ q) @ V
//   q: [256] f32, K: [131072, 256] f32, V: [131072, 256] f32 -> y: [256] f32
// Pass1 (unchanged, measured at HBM roofline ~8.4TB/s): per-CTA online-softmax
// partials. Pass2 rewritten as parallel 3-stage combine (old single-block
// version was latency-bound at 80us).

#define M_TOTAL   131072
#define DIM       256
#define NUM_CTAS  1024
#define ROWS_PER_CTA (M_TOTAL / NUM_CTAS)     // 128
#define NWARPS    8
#define ROWS_PER_WARP (ROWS_PER_CTA / NWARPS) // 16

#define NB2       32                 // pass2b blocks
#define I_PER_B2  (NUM_CTAS / NB2)   // 32 partials per pass2b block

// Scratch (allocation-free): ~1.05 MB
__device__ float g_part[NUM_CTAS][DIM];
__device__ float g_m[NUM_CTAS];
__device__ float g_l[NUM_CTAS];
__device__ float g_sf[NUM_CTAS];
__device__ float g_invL;
__device__ float g_part2[NB2][DIM];

__global__ __launch_bounds__(256)
void sqa_pass1(const float* __restrict__ q,
               const float* __restrict__ K,
               const float* __restrict__ V) {
    const int tid  = threadIdx.x;
    const int warp = tid >> 5;
    const int lane = tid & 31;

    const float4 q0 = reinterpret_cast<const float4*>(q)[lane];
    const float4 q1 = reinterpret_cast<const float4*>(q)[lane + 32];

    const int row0 = blockIdx.x * ROWS_PER_CTA + warp * ROWS_PER_WARP;

    float m = -CUDART_INF_F;
    float l = 0.0f;
    float4 a0 = make_float4(0.f, 0.f, 0.f, 0.f);
    float4 a1 = make_float4(0.f, 0.f, 0.f, 0.f);

    #pragma unroll 2
    for (int r = 0; r < ROWS_PER_WARP; ++r) {
        const size_t row = (size_t)(row0 + r);
        const float4* Kr = reinterpret_cast<const float4*>(K + row * DIM);
        const float4* Vr = reinterpret_cast<const float4*>(V + row * DIM);

        const float4 k0 = Kr[lane];
        const float4 k1 = Kr[lane + 32];
        const float4 v0 = Vr[lane];
        const float4 v1 = Vr[lane + 32];

        float d = k0.x * q0.x + k0.y * q0.y + k0.z * q0.z + k0.w * q0.w
                + k1.x * q1.x + k1.y * q1.y + k1.z * q1.z + k1.w * q1.w;
        #pragma unroll
        for (int off = 16; off > 0; off >>= 1)
            d += __shfl_xor_sync(0xffffffffu, d, off);

        const float mnew  = fmaxf(m, d);
        const float scale = __expf(m - mnew);   // exp(-inf)=0 on first iter
        const float w     = __expf(d - mnew);
        l = l * scale + w;
        a0.x = a0.x * scale + w * v0.x;
        a0.y = a0.y * scale + w * v0.y;
        a0.z = a0.z * scale + w * v0.z;
        a0.w = a0.w * scale + w * v0.w;
        a1.x = a1.x * scale + w * v1.x;
        a1.y = a1.y * scale + w * v1.y;
        a1.z = a1.z * scale + w * v1.z;
        a1.w = a1.w * scale + w * v1.w;
        m = mnew;
    }

    __shared__ float s_m[NWARPS];
    __shared__ float s_l[NWARPS];
    __shared__ float s_acc[NWARPS][DIM];

    if (lane == 0) { s_m[warp] = m; s_l[warp] = l; }
    float* dst = s_acc[warp];
    dst[lane * 4 + 0]       = a0.x;
    dst[lane * 4 + 1]       = a0.y;
    dst[lane * 4 + 2]       = a0.z;
    dst[lane * 4 + 3]       = a0.w;
    dst[128 + lane * 4 + 0] = a1.x;
    dst[128 + lane * 4 + 1] = a1.y;
    dst[128 + lane * 4 + 2] = a1.z;
    dst[128 + lane * 4 + 3] = a1.w;
    __syncthreads();

    float bm = s_m[0];
    #pragma unroll
    for (int w2 = 1; w2 < NWARPS; ++w2) bm = fmaxf(bm, s_m[w2]);

    float y = 0.0f;
    float L = 0.0f;
    #pragma unroll
    for (int w2 = 0; w2 < NWARPS; ++w2) {
        const float sf = __expf(s_m[w2] - bm);
        y += s_acc[w2][tid] * sf;
        L += s_l[w2] * sf;
    }

    g_part[blockIdx.x][tid] = y;
    if (tid == 0) { g_m[blockIdx.x] = bm; g_l[blockIdx.x] = L; }
}

// pass2a: 1 block x 1024 threads. Global max, scale factors, invL.
__global__ __launch_bounds__(1024)
void sqa_pass2a() {
    __shared__ float red[1024];
    const int t = threadIdx.x;

    const float mi = g_m[t];
    red[t] = mi;
    __syncthreads();
    #pragma unroll
    for (int s = 512; s > 0; s >>= 1) {
        if (t < s) red[t] = fmaxf(red[t], red[t + s]);
        __syncthreads();
    }
    const float gmax = red[0];
    __syncthreads();

    const float e = __expf(mi - gmax);
    g_sf[t] = e;
    red[t] = g_l[t] * e;
    __syncthreads();
    #pragma unroll
    for (int s = 512; s > 0; s >>= 1) {
        if (t < s) red[t] += red[t + s];
        __syncthreads();
    }
    if (t == 0) g_invL = 1.0f / red[0];
}

// pass2b: NB2 blocks x 256 threads. Block b sums I_PER_B2 scaled partials.
__global__ __launch_bounds__(256)
void sqa_pass2b() {
    const int t  = threadIdx.x;
    const int i0 = blockIdx.x * I_PER_B2;

    __shared__ float s_sf[I_PER_B2];
    if (t < I_PER_B2) s_sf[t] = g_sf[i0 + t];
    __syncthreads();

    float acc = 0.0f;
    #pragma unroll
    for (int j = 0; j < I_PER_B2; ++j)
        acc += g_part[i0 + j][t] * s_sf[j];

    g_part2[blockIdx.x][t] = acc;
}

// pass2c: 1 block x 256 threads. Sum NB2 row-partials (L2-hot), normalize.
__global__ __launch_bounds__(256)
void sqa_pass2c(float* __restrict__ out) {
    const int t = threadIdx.x;
    float acc = 0.0f;
    #pragma unroll
    for (int j = 0; j < NB2; ++j)
        acc += g_part2[j][t];
    out[t] = acc * g_invL;
}

extern "C" void kernel_launch(void* const* d_in, const int* in_sizes, int n_in,
                              void* d_out, int out_size) {
    const float* q = (const float*)d_in[0];
    const float* K = (const float*)d_in[1];
    const float* V = (const float*)d_in[2];
    float* out = (float*)d_out;

    sqa_pass1<<<NUM_CTAS, 256>>>(q, K, V);
    sqa_pass2a<<<1, 1024>>>();
    sqa_pass2b<<<NB2, 256>>>();
    sqa_pass2c<<<1, 256>>>(out);
}